// round 6
// baseline (speedup 1.0000x reference)
#include <cuda_runtime.h>

// predict/target: [2, 4, 64, 256, 256] fp32 -> 512 slices of 65536 elems.
#define HW              65536
#define NSLICES         512
#define SLICE_D         64
#define NPAIRS          8
#define TPB             128
#define CTAS_PER_SLICE  8
#define GRID            (NSLICES * CTAS_PER_SLICE)       // 4096
#define CHUNK_F4        (HW / 4 / CTAS_PER_SLICE)        // 2048 float4 per CTA
#define BATCH           4
#define NBATCH          (CHUNK_F4 / (TPB * BATCH))       // 4 batches per thread

__device__ float        g_num[NSLICES];
__device__ float        g_sp [NSLICES];
__device__ float        g_st [NSLICES];
__device__ unsigned int g_done;

// sigmoid(x) = 0.5 * tanh(0.5 x) + 0.5  (tanh.approx.f32: 1 MUFU op)
__device__ __forceinline__ float fast_sigmoid(float x) {
    float t;
    asm("tanh.approx.f32 %0, %1;" : "=f"(t) : "f"(x * 0.5f));
    return fmaf(0.5f, t, 0.5f);
}

__device__ __forceinline__ void accum4(const float4& a, const float4& b,
                                       float& num, float& sp, float& st) {
    float s0 = fast_sigmoid(a.x);
    float s1 = fast_sigmoid(a.y);
    float s2 = fast_sigmoid(a.z);
    float s3 = fast_sigmoid(a.w);
    num += s0 * b.x + s1 * b.y + s2 * b.z + s3 * b.w;
    sp  += s0 + s1 + s2 + s3;
    st  += b.x + b.y + b.z + b.w;
}

__global__ __launch_bounds__(TPB)
void dice_fused_kernel(const float* __restrict__ predict,
                       const float* __restrict__ target,
                       float* __restrict__ out) {
    const int cta  = blockIdx.x;
    const int s    = cta / CTAS_PER_SLICE;
    const int part = cta % CTAS_PER_SLICE;
    const int tid  = threadIdx.x;

    const size_t base = (size_t)s * (HW / 4) + (size_t)part * CHUNK_F4 + tid;
    const float4* __restrict__ p = reinterpret_cast<const float4*>(predict) + base;
    const float4* __restrict__ t = reinterpret_cast<const float4*>(target)  + base;

    float num = 0.0f, sp = 0.0f, st = 0.0f;

    // Register double-buffer: loads for batch i+1 are in flight while batch i
    // computes, so every warp keeps 8 LDG.128 outstanding continuously.
    float4 A[2][BATCH], B[2][BATCH];

    #pragma unroll
    for (int j = 0; j < BATCH; ++j) {
        A[0][j] = __ldcs(p + j * TPB);
        B[0][j] = __ldcs(t + j * TPB);
    }

    #pragma unroll
    for (int it = 0; it < NBATCH - 1; ++it) {
        const int cur = it & 1, nxt = cur ^ 1;
        const int off = (it + 1) * (BATCH * TPB);
        #pragma unroll
        for (int j = 0; j < BATCH; ++j) {
            A[nxt][j] = __ldcs(p + off + j * TPB);
            B[nxt][j] = __ldcs(t + off + j * TPB);
        }
        #pragma unroll
        for (int j = 0; j < BATCH; ++j)
            accum4(A[cur][j], B[cur][j], num, sp, st);
    }
    {
        const int cur = (NBATCH - 1) & 1;
        #pragma unroll
        for (int j = 0; j < BATCH; ++j)
            accum4(A[cur][j], B[cur][j], num, sp, st);
    }

    // Warp reduce the three accumulators.
    #pragma unroll
    for (int off = 16; off > 0; off >>= 1) {
        num += __shfl_down_sync(0xffffffffu, num, off);
        sp  += __shfl_down_sync(0xffffffffu, sp,  off);
        st  += __shfl_down_sync(0xffffffffu, st,  off);
    }

    __shared__ float s_num[TPB / 32];
    __shared__ float s_sp [TPB / 32];
    __shared__ float s_st [TPB / 32];
    __shared__ bool  s_last;

    const int lane = tid & 31;
    const int wid  = tid >> 5;
    if (lane == 0) { s_num[wid] = num; s_sp[wid] = sp; s_st[wid] = st; }
    __syncthreads();

    if (tid == 0) {
        float n = 0.0f, a = 0.0f, b = 0.0f;
        #pragma unroll
        for (int w = 0; w < TPB / 32; w++) { n += s_num[w]; a += s_sp[w]; b += s_st[w]; }
        atomicAdd(&g_num[s], n);
        atomicAdd(&g_sp [s], a);
        atomicAdd(&g_st [s], b);
        __threadfence();
        unsigned int d = atomicAdd(&g_done, 1u);
        s_last = (d == GRID - 1);
    }
    __syncthreads();

    // ---- Fused finalize: last CTA reduces all 512 slices ----
    if (s_last) {
        __threadfence();  // acquire: all producer atomics visible

        __shared__ float p_sum[NPAIRS];
        __shared__ float p_cnt[NPAIRS];
        if (tid < NPAIRS) { p_sum[tid] = 0.0f; p_cnt[tid] = 0.0f; }
        __syncthreads();

        for (int i = tid; i < NSLICES; i += TPB) {
            float n = g_num[i];
            float a = g_sp [i];
            float b = g_st [i];
            float dice = 1.0f - 2.0f * n / (a + b + 1.0f);
            float v = (target[(size_t)i * HW] != -1.0f) ? 1.0f : 0.0f;
            atomicAdd(&p_sum[i / SLICE_D], dice * v);
            atomicAdd(&p_cnt[i / SLICE_D], v);
            // Reset state for the next graph replay.
            g_num[i] = 0.0f; g_sp[i] = 0.0f; g_st[i] = 0.0f;
        }
        __syncthreads();

        if (tid == 0) {
            float acc = 0.0f;
            #pragma unroll
            for (int i = 0; i < NPAIRS; i++) acc += p_sum[i] / p_cnt[i];
            out[0] = acc * (1.0f / (float)NPAIRS);
            g_done = 0u;
        }
    }
}

extern "C" void kernel_launch(void* const* d_in, const int* in_sizes, int n_in,
                              void* d_out, int out_size) {
    const float* predict = (const float*)d_in[0];
    const float* target  = (const float*)d_in[1];
    float* out = (float*)d_out;

    dice_fused_kernel<<<GRID, TPB>>>(predict, target, out);
}

// round 8
// speedup vs baseline: 1.1901x; 1.1901x over previous
#include <cuda_runtime.h>
#include <cstdint>

// predict/target: [2, 4, 64, 256, 256] fp32 -> 512 slices of 65536 elems.
#define HW              65536
#define NSLICES         512
#define SLICE_D         64
#define NPAIRS          8
#define TPB             256
#define CTAS_PER_SLICE  8
#define GRID            (NSLICES * CTAS_PER_SLICE)       // 4096
#define CHUNK_F4        (HW / 4 / CTAS_PER_SLICE)        // 2048 float4 per CTA/tensor
#define STAGE_F4        512                              // 8KB per tensor per stage
#define NSTAGES         (CHUNK_F4 / STAGE_F4)            // 4
#define F4_PER_THREAD   (STAGE_F4 / TPB)                 // 2

__device__ float        g_num[NSLICES];
__device__ float        g_sp [NSLICES];
__device__ float        g_st [NSLICES];
__device__ unsigned int g_done;

// sigmoid(x) = 0.5 * tanh(0.5 x) + 0.5  (tanh.approx.f32: 1 MUFU op)
__device__ __forceinline__ float fast_sigmoid(float x) {
    float t;
    asm("tanh.approx.f32 %0, %1;" : "=f"(t) : "f"(x * 0.5f));
    return fmaf(0.5f, t, 0.5f);
}

__device__ __forceinline__ void accum4(const float4& a, const float4& b,
                                       float& num, float& sp, float& st) {
    float s0 = fast_sigmoid(a.x);
    float s1 = fast_sigmoid(a.y);
    float s2 = fast_sigmoid(a.z);
    float s3 = fast_sigmoid(a.w);
    num += s0 * b.x + s1 * b.y + s2 * b.z + s3 * b.w;
    sp  += s0 + s1 + s2 + s3;
    st  += b.x + b.y + b.z + b.w;
}

__device__ __forceinline__ void cp_async16(void* smem_dst, const void* gmem_src) {
    unsigned int s = (unsigned int)__cvta_generic_to_shared(smem_dst);
    asm volatile("cp.async.cg.shared.global [%0], [%1], 16;" :: "r"(s), "l"(gmem_src));
}

__global__ __launch_bounds__(TPB)
void dice_fused_kernel(const float* __restrict__ predict,
                       const float* __restrict__ target,
                       float* __restrict__ out) {
    // Double-buffered staging: [buf][tensor][idx] = 2*2*512 float4 = 32 KB.
    __shared__ float4 sbuf[2][2][STAGE_F4];

    const int cta  = blockIdx.x;
    const int s    = cta / CTAS_PER_SLICE;
    const int part = cta % CTAS_PER_SLICE;
    const int tid  = threadIdx.x;

    const size_t base = (size_t)s * (HW / 4) + (size_t)part * CHUNK_F4;
    const float4* __restrict__ p = reinterpret_cast<const float4*>(predict) + base;
    const float4* __restrict__ t = reinterpret_cast<const float4*>(target)  + base;

    // Each thread copies (and later reads back) ITS OWN elements:
    // indices {tid, tid+TPB} within each stage. No cross-thread smem traffic,
    // so no __syncthreads needed inside the pipeline.

    // Prefetch stage 0.
    #pragma unroll
    for (int j = 0; j < F4_PER_THREAD; ++j) {
        const int idx = tid + j * TPB;
        cp_async16(&sbuf[0][0][idx], p + idx);
        cp_async16(&sbuf[0][1][idx], t + idx);
    }
    asm volatile("cp.async.commit_group;");

    float num = 0.0f, sp = 0.0f, st = 0.0f;

    #pragma unroll
    for (int it = 0; it < NSTAGES; ++it) {
        const int cur = it & 1;
        if (it + 1 < NSTAGES) {
            const int nxt = cur ^ 1;
            const int off = (it + 1) * STAGE_F4;
            #pragma unroll
            for (int j = 0; j < F4_PER_THREAD; ++j) {
                const int idx = tid + j * TPB;
                cp_async16(&sbuf[nxt][0][idx], p + off + idx);
                cp_async16(&sbuf[nxt][1][idx], t + off + idx);
            }
            asm volatile("cp.async.commit_group;");
            asm volatile("cp.async.wait_group 1;");
        } else {
            asm volatile("cp.async.wait_group 0;");
        }

        #pragma unroll
        for (int j = 0; j < F4_PER_THREAD; ++j) {
            const int idx = tid + j * TPB;
            accum4(sbuf[cur][0][idx], sbuf[cur][1][idx], num, sp, st);
        }
    }

    // Warp reduce the three accumulators.
    #pragma unroll
    for (int off = 16; off > 0; off >>= 1) {
        num += __shfl_down_sync(0xffffffffu, num, off);
        sp  += __shfl_down_sync(0xffffffffu, sp,  off);
        st  += __shfl_down_sync(0xffffffffu, st,  off);
    }

    __shared__ float s_num[TPB / 32];
    __shared__ float s_sp [TPB / 32];
    __shared__ float s_st [TPB / 32];
    __shared__ bool  s_last;

    const int lane = tid & 31;
    const int wid  = tid >> 5;
    if (lane == 0) { s_num[wid] = num; s_sp[wid] = sp; s_st[wid] = st; }
    __syncthreads();

    if (tid == 0) {
        float n = 0.0f, a = 0.0f, b = 0.0f;
        #pragma unroll
        for (int w = 0; w < TPB / 32; w++) { n += s_num[w]; a += s_sp[w]; b += s_st[w]; }
        atomicAdd(&g_num[s], n);
        atomicAdd(&g_sp [s], a);
        atomicAdd(&g_st [s], b);
        __threadfence();
        unsigned int d = atomicAdd(&g_done, 1u);
        s_last = (d == GRID - 1);
    }
    __syncthreads();

    // ---- Fused finalize: last CTA reduces all 512 slices ----
    if (s_last) {
        __threadfence();  // acquire: all producer atomics visible

        __shared__ float p_sum[NPAIRS];
        __shared__ float p_cnt[NPAIRS];
        if (tid < NPAIRS) { p_sum[tid] = 0.0f; p_cnt[tid] = 0.0f; }
        __syncthreads();

        for (int i = tid; i < NSLICES; i += TPB) {
            float n = g_num[i];
            float a = g_sp [i];
            float b = g_st [i];
            float dice = 1.0f - 2.0f * n / (a + b + 1.0f);
            float v = (target[(size_t)i * HW] != -1.0f) ? 1.0f : 0.0f;
            atomicAdd(&p_sum[i / SLICE_D], dice * v);
            atomicAdd(&p_cnt[i / SLICE_D], v);
            // Reset state for the next graph replay.
            g_num[i] = 0.0f; g_sp[i] = 0.0f; g_st[i] = 0.0f;
        }
        __syncthreads();

        if (tid == 0) {
            float acc = 0.0f;
            #pragma unroll
            for (int i = 0; i < NPAIRS; i++) acc += p_sum[i] / p_cnt[i];
            out[0] = acc * (1.0f / (float)NPAIRS);
            g_done = 0u;
        }
    }
}

extern "C" void kernel_launch(void* const* d_in, const int* in_sizes, int n_in,
                              void* d_out, int out_size) {
    const float* predict = (const float*)d_in[0];
    const float* target  = (const float*)d_in[1];
    float* out = (float*)d_out;

    dice_fused_kernel<<<GRID, TPB>>>(predict, target, out);
}